// round 5
// baseline (speedup 1.0000x reference)
#include <cuda_runtime.h>

// Unitary gate on wires {5,13} of a 26-wire register (target bits 20 and 12).
// out[b + off] = U[4x4] @ x[b + off], off ∈ {0, 2^12, 2^20, 2^20+2^12}.
//
// DRAM-bound streaming kernel, 512 MB total traffic.
// R4: persistent grid-stride (148*8 blocks resident, ~14 iterations each) to
// remove per-block ramp bubbles; 512-thread blocks; streaming hints kept.

static constexpr unsigned REST     = 1u << 24;     // rest-index count
static constexpr unsigned NTHREADS = REST / 4;     // one float4-group per iteration

static constexpr unsigned OFF12_V4 = (1u << 12) >> 2;  // stream offsets in float4 units
static constexpr unsigned OFF20_V4 = (1u << 20) >> 2;

static constexpr unsigned BLOCK  = 512;
static constexpr unsigned GRID   = 148 * 8;            // 1184 resident blocks
static constexpr unsigned STRIDE = GRID * BLOCK;       // 606208

__global__ __launch_bounds__(BLOCK)
void unitary_gate_kernel(const float4* __restrict__ x4,
                         const float*  __restrict__ U,
                         float4*       __restrict__ o4)
{
    // Gate matrix (broadcast, L2-resident) — loaded once per thread.
    float u00 = __ldg(U +  0), u01 = __ldg(U +  1), u02 = __ldg(U +  2), u03 = __ldg(U +  3);
    float u10 = __ldg(U +  4), u11 = __ldg(U +  5), u12 = __ldg(U +  6), u13 = __ldg(U +  7);
    float u20 = __ldg(U +  8), u21 = __ldg(U +  9), u22 = __ldg(U + 10), u23 = __ldg(U + 11);
    float u30 = __ldg(U + 12), u31 = __ldg(U + 13), u32 = __ldg(U + 14), u33 = __ldg(U + 15);

    for (unsigned r = blockIdx.x * BLOCK + threadIdx.x; r < NTHREADS; r += STRIDE) {
        unsigned rr = r << 2;  // rest index (multiple of 4)

        // Insert zero bits at positions 12 and 20 of the flat amplitude index:
        //   rr bits [0..11]  -> base bits [0..11]
        //   rr bits [12..18] -> base bits [13..19]
        //   rr bits [19..23] -> base bits [21..25]
        unsigned base = (rr & 0x00000FFFu)
                      | ((rr & 0x0007F000u) << 1)
                      | ((rr & 0x00F80000u) << 2);
        unsigned i0 = base >> 2;  // float4 index (base is a multiple of 4)

        // Front-batched streaming loads (MLP=4, evict-first).
        float4 s0 = __ldcs(x4 + i0);
        float4 s1 = __ldcs(x4 + i0 + OFF12_V4);
        float4 s2 = __ldcs(x4 + i0 + OFF20_V4);
        float4 s3 = __ldcs(x4 + i0 + OFF20_V4 + OFF12_V4);

        float4 d0, d1, d2, d3;
        d0.x = u00*s0.x + u01*s1.x + u02*s2.x + u03*s3.x;
        d0.y = u00*s0.y + u01*s1.y + u02*s2.y + u03*s3.y;
        d0.z = u00*s0.z + u01*s1.z + u02*s2.z + u03*s3.z;
        d0.w = u00*s0.w + u01*s1.w + u02*s2.w + u03*s3.w;

        d1.x = u10*s0.x + u11*s1.x + u12*s2.x + u13*s3.x;
        d1.y = u10*s0.y + u11*s1.y + u12*s2.y + u13*s3.y;
        d1.z = u10*s0.z + u11*s1.z + u12*s2.z + u13*s3.z;
        d1.w = u10*s0.w + u11*s1.w + u12*s2.w + u13*s3.w;

        d2.x = u20*s0.x + u21*s1.x + u22*s2.x + u23*s3.x;
        d2.y = u20*s0.y + u21*s1.y + u22*s2.y + u23*s3.y;
        d2.z = u20*s0.z + u21*s1.z + u22*s2.z + u23*s3.z;
        d2.w = u20*s0.w + u21*s1.w + u22*s2.w + u23*s3.w;

        d3.x = u30*s0.x + u31*s1.x + u32*s2.x + u33*s3.x;
        d3.y = u30*s0.y + u31*s1.y + u32*s2.y + u33*s3.y;
        d3.z = u30*s0.z + u31*s1.z + u32*s2.z + u33*s3.z;
        d3.w = u30*s0.w + u31*s1.w + u32*s2.w + u33*s3.w;

        __stcs(o4 + i0,                       d0);
        __stcs(o4 + i0 + OFF12_V4,            d1);
        __stcs(o4 + i0 + OFF20_V4,            d2);
        __stcs(o4 + i0 + OFF20_V4 + OFF12_V4, d3);
    }
}

extern "C" void kernel_launch(void* const* d_in, const int* in_sizes, int n_in,
                              void* d_out, int out_size)
{
    const float* x = (const float*)d_in[0];
    const float* U = (const float*)d_in[1];
    if (n_in >= 2 && in_sizes[0] == 16) {  // defensive: swapped order
        U = (const float*)d_in[0];
        x = (const float*)d_in[1];
    }
    float* out = (float*)d_out;

    unitary_gate_kernel<<<GRID, BLOCK>>>(
        (const float4*)x, U, (float4*)out);
}

// round 6
// speedup vs baseline: 1.0274x; 1.0274x over previous
#include <cuda_runtime.h>

// Unitary gate on wires {5,13} of a 26-wire register (target bits 20 and 12).
// out[b + off] = U[4x4] @ x[b + off], off ∈ {0, 2^12, 2^20, 2^20+2^12}.
//
// DRAM-bound streaming kernel, 512 MB total traffic.
// R6 = R3 (best base: 4 x float4 / thread, 32 regs, 86% occ, streaming hints)
// + vectorized U load (4 x LDG.128 instead of 16 scalar LDGs) to cut L1tex
// wavefront pressure ahead of the DRAM-bound stream loads.

static constexpr unsigned REST    = 1u << 24;   // rest-index count
static constexpr unsigned THREADS = REST / 4;   // 4 consecutive rest positions / thread

static constexpr unsigned OFF12_V4 = (1u << 12) >> 2;  // stream offsets in float4 units
static constexpr unsigned OFF20_V4 = (1u << 20) >> 2;

__global__ __launch_bounds__(256, 8)
void unitary_gate_kernel(const float4* __restrict__ x4,
                         const float4* __restrict__ U4,
                         float4*       __restrict__ o4)
{
    unsigned r  = blockIdx.x * blockDim.x + threadIdx.x;   // 0 .. 2^22-1
    unsigned rr = r << 2;                                  // rest index (multiple of 4)

    // Insert zero bits at positions 12 and 20 of the flat amplitude index:
    //   rr bits [0..11]  -> base bits [0..11]
    //   rr bits [12..18] -> base bits [13..19]
    //   rr bits [19..23] -> base bits [21..25]
    unsigned base = (rr & 0x00000FFFu)
                  | ((rr & 0x0007F000u) << 1)
                  | ((rr & 0x00F80000u) << 2);
    unsigned i0 = base >> 2;  // float4 index (base is a multiple of 4)

    // Gate matrix: 4 x 128-bit broadcast loads (L1/L2-resident).
    float4 u0 = __ldg(U4 + 0);   // row 0
    float4 u1 = __ldg(U4 + 1);   // row 1
    float4 u2 = __ldg(U4 + 2);   // row 2
    float4 u3 = __ldg(U4 + 3);   // row 3

    // Front-batched streaming loads (MLP=4, evict-first).
    float4 s0 = __ldcs(x4 + i0);
    float4 s1 = __ldcs(x4 + i0 + OFF12_V4);
    float4 s2 = __ldcs(x4 + i0 + OFF20_V4);
    float4 s3 = __ldcs(x4 + i0 + OFF20_V4 + OFF12_V4);

    float4 d0, d1, d2, d3;
    d0.x = u0.x*s0.x + u0.y*s1.x + u0.z*s2.x + u0.w*s3.x;
    d0.y = u0.x*s0.y + u0.y*s1.y + u0.z*s2.y + u0.w*s3.y;
    d0.z = u0.x*s0.z + u0.y*s1.z + u0.z*s2.z + u0.w*s3.z;
    d0.w = u0.x*s0.w + u0.y*s1.w + u0.z*s2.w + u0.w*s3.w;

    d1.x = u1.x*s0.x + u1.y*s1.x + u1.z*s2.x + u1.w*s3.x;
    d1.y = u1.x*s0.y + u1.y*s1.y + u1.z*s2.y + u1.w*s3.y;
    d1.z = u1.x*s0.z + u1.y*s1.z + u1.z*s2.z + u1.w*s3.z;
    d1.w = u1.x*s0.w + u1.y*s1.w + u1.z*s2.w + u1.w*s3.w;

    d2.x = u2.x*s0.x + u2.y*s1.x + u2.z*s2.x + u2.w*s3.x;
    d2.y = u2.x*s0.y + u2.y*s1.y + u2.z*s2.y + u2.w*s3.y;
    d2.z = u2.x*s0.z + u2.y*s1.z + u2.z*s2.z + u2.w*s3.z;
    d2.w = u2.x*s0.w + u2.y*s1.w + u2.z*s2.w + u2.w*s3.w;

    d3.x = u3.x*s0.x + u3.y*s1.x + u3.z*s2.x + u3.w*s3.x;
    d3.y = u3.x*s0.y + u3.y*s1.y + u3.z*s2.y + u3.w*s3.y;
    d3.z = u3.x*s0.z + u3.y*s1.z + u3.z*s2.z + u3.w*s3.z;
    d3.w = u3.x*s0.w + u3.y*s1.w + u3.z*s2.w + u3.w*s3.w;

    __stcs(o4 + i0,                       d0);
    __stcs(o4 + i0 + OFF12_V4,            d1);
    __stcs(o4 + i0 + OFF20_V4,            d2);
    __stcs(o4 + i0 + OFF20_V4 + OFF12_V4, d3);
}

extern "C" void kernel_launch(void* const* d_in, const int* in_sizes, int n_in,
                              void* d_out, int out_size)
{
    const float* x = (const float*)d_in[0];
    const float* U = (const float*)d_in[1];
    if (n_in >= 2 && in_sizes[0] == 16) {  // defensive: swapped order
        U = (const float*)d_in[0];
        x = (const float*)d_in[1];
    }
    float* out = (float*)d_out;

    const unsigned threads = 256;
    const unsigned blocks  = THREADS / threads;  // 16384
    unitary_gate_kernel<<<blocks, threads>>>(
        (const float4*)x, (const float4*)U, (float4*)out);
}